// round 12
// baseline (speedup 1.0000x reference)
#include <cuda_runtime.h>
#include <math.h>

#define BB 4
#define CC 3
#define HH 384
#define WW 384
#define HWSZ (HH * WW)
#define CHW (CC * HWSZ)

#define INV2SC 50.0f            // 1/(2*0.1^2)
#define INV2SS (1.0f / 98.0f)   // 1/(2*7^2)
#define EPS_LP 1e-6f

// Border pixels per image: 2 strips of 3x384 + 378 rows x 6 cols
#define NBORDER (2 * 3 * WW + (HH - 6) * 6)   // 4572
#define NBTOT (NBORDER * BB)                  // 18288
#define NBBLK ((NBTOT + 255) / 256)           // 72

// lp(d) = (d*d + eps)^0.4
__device__ __forceinline__ float lp_term(float d) {
    return __powf(fmaf(d, d, EPS_LP), 0.4f);
}

// warp -> block reduction; tid is the LINEAR 0..255 thread id.
__device__ __forceinline__ void reduce_add(float acc, float* out, int tid) {
    const unsigned FULL = 0xFFFFFFFFu;
#pragma unroll
    for (int off = 16; off > 0; off >>= 1)
        acc += __shfl_down_sync(FULL, acc, off);
    __shared__ float wsum[8];
    const int wid = tid >> 5, lid = tid & 31;
    if (lid == 0) wsum[wid] = acc;
    __syncthreads();
    if (wid == 0) {
        float v = (lid < 8) ? wsum[lid] : 0.0f;
#pragma unroll
        for (int off = 4; off > 0; off >>= 1)
            v += __shfl_down_sync(FULL, v, off);
        if (lid == 0) {
            const float inv_n = 1.0f / (float)(BB * CC * HH * WW);
            atomicAdd(out, v * inv_n);
        }
    }
}

// One ordered half-set term (exact same fp32 ops as all passing rounds).
__device__ __forceinline__ float half_term(
    const float* __restrict__ pi, const float* __restrict__ pt, int q,
    float i0, float i1, float i2, float t0, float t1, float t2,
    float ws, float sconst)
{
    const float iq0 = __ldg(pi + q);
    const float iq1 = __ldg(pi + q + HWSZ);
    const float iq2 = __ldg(pi + q + 2 * HWSZ);
    const float tq0 = __ldg(pt + q);
    const float tq1 = __ldg(pt + q + HWSZ);
    const float tq2 = __ldg(pt + q + 2 * HWSZ);

    const float d0 = i0 - iq0, d1 = i1 - iq1, d2 = i2 - iq2;
    const float e0 = t0 - tq0, e1 = t1 - tq1, e2 = t2 - tq2;

    const float cd = fmaf(e0, e0, fmaf(e1, e1, e2 * e2));
    const float wcs = __expf(-fmaf(cd, INV2SC, sconst));   // ws*wc fused

    const float sm = lp_term(d0) + lp_term(d1) + lp_term(d2);
    const float ed = lp_term(fabsf(d0) - fabsf(e0))
                   + lp_term(fabsf(d1) - fabsf(e1))
                   + lp_term(fabsf(d2) - fabsf(e2));

    return fmaf(wcs, sm, (ws - wcs) * ed);
}

// Border path: clamped (out-of-bounds) ordered terms, weight 1. z == 0 slice,
// scheduled first so it overlaps the hot waves.
__device__ __noinline__ void border_path(const float* __restrict__ inp,
                                         const float* __restrict__ tgt,
                                         float* __restrict__ out, int tid) {
    const int bid = blockIdx.y * gridDim.x + blockIdx.x;
    const int gid = bid * 256 + tid;
    float acc = 0.0f;

    if (gid < NBTOT) {
        const int b = gid / NBORDER;
        const int r = gid % NBORDER;
        int x, y;
        if (r < 3 * WW) {                    // top rows 0..2
            y = r / WW; x = r % WW;
        } else if (r < 6 * WW) {             // bottom rows 381..383
            const int r2 = r - 3 * WW;
            y = (HH - 3) + r2 / WW; x = r2 % WW;
        } else {                             // side cols, rows 3..380
            const int r3 = r - 6 * WW;
            y = 3 + r3 / 6;
            const int c = r3 % 6;
            x = (c < 3) ? c : (WW - 6 + c);
        }
        const int pidx = y * WW + x;
        const float* pi = inp + b * CHW + pidx;
        const float* pt = tgt + b * CHW + pidx;

        const float i0 = pi[0], i1 = pi[HWSZ], i2 = pi[2 * HWSZ];
        const float t0 = pt[0], t1 = pt[HWSZ], t2 = pt[2 * HWSZ];

        float wky[4];
        wky[0] = 1.0f;
        wky[1] = __expf(-1.0f * INV2SS);
        wky[2] = __expf(-4.0f * INV2SS);
        wky[3] = __expf(-9.0f * INV2SS);

#pragma unroll 1
        for (int dy = -3; dy <= 3; dy++) {
#pragma unroll 1
            for (int dx = -3; dx <= 3; dx++) {
                if (dy == 0 && dx == 0) continue;
                int qx = x + dx, qy = y + dy;
                const bool oob = ((unsigned)qx >= (unsigned)WW) ||
                                 ((unsigned)qy >= (unsigned)HH);
                if (oob) {
                    qx = qx < 0 ? 0 : (qx >= WW ? WW - 1 : qx);
                    qy = qy < 0 ? 0 : (qy >= HH ? HH - 1 : qy);
                    const int q = (qy - y) * WW + (qx - x);
                    const int ady = dy < 0 ? -dy : dy;
                    const int adx = dx < 0 ? -dx : dx;
                    const float ws = wky[ady] * wky[adx];
                    const float sconst = (float)(dy * dy + dx * dx) * INV2SS;
                    acc += half_term(pi, pt, q, i0, i1, i2, t0, t1, t2,
                                     ws, sconst);
                }
            }
        }
    }
    reduce_add(acc, out, tid);
}

// Edge-column blocks (blockIdx.x 0 or 11): compact ROLLED checked half-set.
// Small (~2KB) so the interior unrolled body stays within I$ limits.
__device__ __noinline__ void edge_path(const float* __restrict__ pi,
                                       const float* __restrict__ pt,
                                       float* __restrict__ out,
                                       int x, int y, int tid) {
    const float i0 = pi[0], i1 = pi[HWSZ], i2 = pi[2 * HWSZ];
    const float t0 = pt[0], t1 = pt[HWSZ], t2 = pt[2 * HWSZ];

    float wky[4];
    wky[0] = 1.0f;
    wky[1] = __expf(-1.0f * INV2SS);
    wky[2] = __expf(-4.0f * INV2SS);
    wky[3] = __expf(-9.0f * INV2SS);

    float pacc = 0.0f;
#pragma unroll 1
    for (int dy = 0; dy <= 3; dy++) {
        if ((y + dy) >= HH) break;
        const int k0 = (dy == 0) ? 1 : -3;
#pragma unroll 1
        for (int dx = k0; dx <= 3; dx++) {
            if ((unsigned)(x + dx) < (unsigned)WW) {
                const int q = dy * WW + dx;
                const int adx = dx < 0 ? -dx : dx;
                const float ws = wky[dy] * wky[adx];
                const float sconst = (float)(dy * dy + dx * dx) * INV2SS;
                pacc += half_term(pi, pt, q, i0, i1, i2, t0, t1, t2,
                                  ws, sconst);
            }
        }
    }

    const float l2 = (i0 - t0) * (i0 - t0)
                   + (i1 - t1) * (i1 - t1)
                   + (i2 - t2) * (i2 - t2);
    reduce_add(fmaf(2.0f, pacc, l2), out, tid);
}

// z == 0: border slice. z >= 1: image b = z-1.
//   interior-column blocks (x in [32,352)): predicate-free unrolled body —
//   all column accesses x+dx in [29,355] are statically in-row; only the
//   warp-uniform row check y+dy < H remains.
//   edge-column blocks: compact rolled checked body.
__global__ __launch_bounds__(256)
void loss_kernel(const float* __restrict__ inp,
                 const float* __restrict__ tgt,
                 float* __restrict__ out) {
    const int tid = threadIdx.y * 32 + threadIdx.x;
    if (blockIdx.z == 0) {
        if (blockIdx.y * gridDim.x + blockIdx.x >= NBBLK) return;
        border_path(inp, tgt, out, tid);
        return;
    }
    const int b = blockIdx.z - 1;
    const int x = blockIdx.x * 32 + threadIdx.x;
    const int y = blockIdx.y * 8 + threadIdx.y;
    const int pidx = y * WW + x;
    const float* pi = inp + b * CHW + pidx;
    const float* pt = tgt + b * CHW + pidx;

    if (blockIdx.x == 0 || blockIdx.x == gridDim.x - 1) {
        edge_path(pi, pt, out, x, y, tid);
        return;
    }

    const float i0 = pi[0], i1 = pi[HWSZ], i2 = pi[2 * HWSZ];
    const float t0 = pt[0], t1 = pt[HWSZ], t2 = pt[2 * HWSZ];

    float wky[4];
    wky[0] = 1.0f;
    wky[1] = __expf(-1.0f * INV2SS);
    wky[2] = __expf(-4.0f * INV2SS);
    wky[3] = __expf(-9.0f * INV2SS);

    float pacc0 = 0.0f, pacc1 = 0.0f;   // dual accumulators (ILP)

#pragma unroll
    for (int dy = 0; dy <= 3; dy++) {
        if ((y + dy) < HH) {            // warp-uniform (threadIdx.y fixed)
#pragma unroll
            for (int dx = -3; dx <= 3; dx++) {
                if (dy == 0 && dx <= 0) continue;   // compile-time skip
                const int q = dy * WW + dx;         // immediate
                const int adx = dx < 0 ? -dx : dx;
                const float ws = wky[dy] * wky[adx];
                const float sconst = (float)(dy * dy + dx * dx) * INV2SS;
                const float t = half_term(pi, pt, q, i0, i1, i2,
                                          t0, t1, t2, ws, sconst);
                if (dx & 1) pacc0 += t; else pacc1 += t;
            }
        }
    }

    const float l2 = (i0 - t0) * (i0 - t0)
                   + (i1 - t1) * (i1 - t1)
                   + (i2 - t2) * (i2 - t2);
    const float acc = fmaf(2.0f, pacc0 + pacc1, l2);

    reduce_add(acc, out, tid);
}

extern "C" void kernel_launch(void* const* d_in, const int* in_sizes, int n_in,
                              void* d_out, int out_size) {
    (void)in_sizes; (void)n_in;
    const float* inp = (const float*)d_in[0];
    const float* tgt = (const float*)d_in[1];
    float* out = (float*)d_out;

    if (out_size >= 1) cudaMemsetAsync(out, 0, sizeof(float));

    dim3 block(32, 8, 1);
    dim3 grid(WW / 32, HH / 8, BB + 1);   // z==0: border; z-1 = image index
    loss_kernel<<<grid, block>>>(inp, tgt, out);
}